// round 5
// baseline (speedup 1.0000x reference)
#include <cuda_runtime.h>
#include <math.h>

#define B_  64
#define T_  256
#define KX  5
#define X_  512
#define H_  512
#define G_  2048   // 4*H
#define F_  1024   // 2*X
#define M_  (B_*T_)

// ---- scratch (static device globals; no runtime allocation) ----
static __device__ float g_xg[(size_t)M_ * F_];          // 64 MB  (b*T+t, 1024)
static __device__ float g_pre[(size_t)T_ * B_ * G_];    // 128 MB (t, b, 2048)
static __device__ float g_h[(size_t)T_ * B_ * H_];      // 32 MB  (t, b, 512) == scan state + history
static __device__ float g_c[B_ * H_];                   // cell state, owner-indexed (race-free in place)
static __device__ float g_scale[T_];
static __device__ float g_shift[T_];

// ------------------------------------------------------------------
// Kernel 0: x_g_t = concat(x[:,:,0,:], mean(x[:,:,1:5,:], axis=2))
// ------------------------------------------------------------------
__global__ void k_build_xg(const float* __restrict__ x)
{
    int idx = blockIdx.x * blockDim.x + threadIdx.x;   // over M_*X_
    if (idx >= M_ * X_) return;
    int col = idx & (X_ - 1);
    int bt  = idx >> 9;                                // b*T + t
    const float* px = x + (size_t)bt * (KX * X_) + col;
    float s = px[0];
    float r = 0.25f * (px[X_] + px[2 * X_] + px[3 * X_] + px[4 * X_]);
    g_xg[(size_t)bt * F_ + col]       = s;
    g_xg[(size_t)bt * F_ + X_ + col]  = r;
}

// ------------------------------------------------------------------
// Kernel 1: pre[t][b][g] = sum_f xg[b*T+t][f] * W_ih[g][f] + (b_ih+b_hh)[g]
// Classic 128x128x8 fp32 SGEMM, 256 threads, 8x8 microtile (split 4+4).
// ------------------------------------------------------------------
#define BM 128
#define BN 128
#define BKK 8

__global__ __launch_bounds__(256, 2)
void k_gemm_pre(const float* __restrict__ Wih,
                const float* __restrict__ bih,
                const float* __restrict__ bhh)
{
    __shared__ float As[BKK][BM];
    __shared__ float Bs[BKK][BN];

    const int tid = threadIdx.x;
    const int m0 = blockIdx.y * BM;
    const int n0 = blockIdx.x * BN;

    // global->smem loaders: one float4 of A and B per thread per k-tile
    const int lr = tid >> 1;            // 0..127 : tile row
    const int lk = (tid & 1) << 2;      // 0 or 4 : k sub-offset

    // compute mapping: 16x16 thread grid, split microtile (4 + 4 at +64)
    const int tr = tid >> 4;            // 0..15
    const int tc = tid & 15;            // 0..15
    const int ra = tr << 2;
    const int cb = tc << 2;

    float acc[8][8];
    #pragma unroll
    for (int i = 0; i < 8; ++i)
        #pragma unroll
        for (int j = 0; j < 8; ++j) acc[i][j] = 0.f;

    const float* Aptr = &g_xg[(size_t)(m0 + lr) * F_ + lk];
    const float* Bptr = &Wih [(size_t)(n0 + lr) * F_ + lk];

    for (int k0 = 0; k0 < F_; k0 += BKK) {
        float4 av = *(const float4*)(Aptr + k0);
        float4 bv = *(const float4*)(Bptr + k0);
        As[lk + 0][lr] = av.x; As[lk + 1][lr] = av.y;
        As[lk + 2][lr] = av.z; As[lk + 3][lr] = av.w;
        Bs[lk + 0][lr] = bv.x; Bs[lk + 1][lr] = bv.y;
        Bs[lk + 2][lr] = bv.z; Bs[lk + 3][lr] = bv.w;
        __syncthreads();
        #pragma unroll
        for (int kk = 0; kk < BKK; ++kk) {
            float a[8], b[8];
            *(float4*)(a)     = *(const float4*)(&As[kk][ra]);
            *(float4*)(a + 4) = *(const float4*)(&As[kk][ra + 64]);
            *(float4*)(b)     = *(const float4*)(&Bs[kk][cb]);
            *(float4*)(b + 4) = *(const float4*)(&Bs[kk][cb + 64]);
            #pragma unroll
            for (int i = 0; i < 8; ++i)
                #pragma unroll
                for (int j = 0; j < 8; ++j)
                    acc[i][j] += a[i] * b[j];
        }
        __syncthreads();
    }

    // epilogue: add bias, permute (b*T+t, g) -> (t, b, g)
    float bias[8];
    #pragma unroll
    for (int j = 0; j < 8; ++j) {
        int col = n0 + cb + ((j < 4) ? j : 60 + j);
        bias[j] = bih[col] + bhh[col];
    }
    #pragma unroll
    for (int i = 0; i < 8; ++i) {
        int m = m0 + ra + ((i < 4) ? i : 60 + i);
        int t = m & (T_ - 1);
        int b = m >> 8;
        float* dst = &g_pre[((size_t)t * B_ + b) * G_ + n0];
        float4 v0 = make_float4(acc[i][0] + bias[0], acc[i][1] + bias[1],
                                acc[i][2] + bias[2], acc[i][3] + bias[3]);
        float4 v1 = make_float4(acc[i][4] + bias[4], acc[i][5] + bias[5],
                                acc[i][6] + bias[6], acc[i][7] + bias[7]);
        *(float4*)(dst + cb)      = v0;
        *(float4*)(dst + cb + 64) = v1;
    }
}

// ------------------------------------------------------------------
// Kernel 2: one LSTM time step. 128 CTAs x 256 threads.
// CTA owns j-range [j0, j0+4) across all 4 gates (16 W_hh rows in smem).
// Thread (b = tid&63, jj = tid>>6) computes all 4 gates for (b, j0+jj).
// t=0: skips recurrent GEMM and cell read => no state init kernels needed.
// ------------------------------------------------------------------
#define SBK 32

__global__ __launch_bounds__(256)
void k_step(const float* __restrict__ Whh, int t)
{
    __shared__ float Ws[16][H_];          // 32 KB : 16 W_hh rows (gate*4+jj)
    __shared__ float Hs[64][SBK + 4];     // 9.2 KB: h chunk, padded (4b+k banks)

    const int tid = threadIdx.x;
    const int j0 = blockIdx.x << 2;
    const int b  = tid & 63;
    const int jj = tid >> 6;
    const int j  = j0 + jj;

    float acc0 = 0.f, acc1 = 0.f, acc2 = 0.f, acc3 = 0.f;

    if (t > 0) {
        // load 16 rows of W_hh: row_local rl = gate*4 + jjl -> global row gate*512 + j0 + jjl
        for (int i = tid; i < 16 * (H_ / 4); i += 256) {
            int rl = i >> 7;                  // 128 float4 per row
            int k4 = (i & 127) << 2;
            int grow = (rl >> 2) * H_ + j0 + (rl & 3);
            *(float4*)&Ws[rl][k4] = *(const float4*)&Whh[(size_t)grow * H_ + k4];
        }

        const float* hprev = &g_h[(size_t)(t - 1) * (B_ * H_)];
        for (int kc = 0; kc < H_; kc += SBK) {
            __syncthreads();
            // load 64 x 32 h chunk (coalesced float4 over k)
            for (int i = tid; i < 512; i += 256) {
                int bb = i >> 3;
                int k4 = (i & 7) << 2;
                *(float4*)&Hs[bb][k4] = *(const float4*)&hprev[(size_t)bb * H_ + kc + k4];
            }
            __syncthreads();
            #pragma unroll
            for (int k = 0; k < SBK; k += 4) {
                float4 a  = *(const float4*)&Hs[b][k];
                float4 w0 = *(const float4*)&Ws[jj     ][kc + k];
                float4 w1 = *(const float4*)&Ws[jj + 4 ][kc + k];
                float4 w2 = *(const float4*)&Ws[jj + 8 ][kc + k];
                float4 w3 = *(const float4*)&Ws[jj + 12][kc + k];
                acc0 += a.x * w0.x; acc0 += a.y * w0.y; acc0 += a.z * w0.z; acc0 += a.w * w0.w;
                acc1 += a.x * w1.x; acc1 += a.y * w1.y; acc1 += a.z * w1.z; acc1 += a.w * w1.w;
                acc2 += a.x * w2.x; acc2 += a.y * w2.y; acc2 += a.z * w2.z; acc2 += a.w * w2.w;
                acc3 += a.x * w3.x; acc3 += a.y * w3.y; acc3 += a.z * w3.z; acc3 += a.w * w3.w;
            }
        }
    }

    const float* prow = &g_pre[((size_t)t * B_ + b) * G_];
    float zi = acc0 + prow[j];
    float zf = acc1 + prow[j + 512];
    float zg = acc2 + prow[j + 1024];
    float zo = acc3 + prow[j + 1536];

    float ig = 1.f / (1.f + expf(-zi));
    float fg = 1.f / (1.f + expf(-zf));
    float gg = tanhf(zg);
    float og = 1.f / (1.f + expf(-zo));

    const int cidx = b * H_ + j;
    float cprev = (t > 0) ? g_c[cidx] : 0.f;
    float c = fg * cprev + ig * gg;
    g_c[cidx] = c;
    g_h[(size_t)t * (B_ * H_) + cidx] = og * tanhf(c);
}

// ------------------------------------------------------------------
// Kernel 3: per-t batchnorm stats over (B,H) -> scale/shift
// ------------------------------------------------------------------
__global__ void k_bnstats(const float* __restrict__ gamma,
                          const float* __restrict__ beta)
{
    const int t   = blockIdx.x;
    const int tid = threadIdx.x;
    const float* p = &g_h[(size_t)t * (B_ * H_)];
    float s = 0.f, s2 = 0.f;
    for (int i = tid; i < B_ * H_; i += 256) {
        float v = p[i];
        s += v; s2 += v * v;
    }
    __shared__ float rs[256], rq[256];
    rs[tid] = s; rq[tid] = s2;
    __syncthreads();
    for (int off = 128; off > 0; off >>= 1) {
        if (tid < off) { rs[tid] += rs[tid + off]; rq[tid] += rq[tid + off]; }
        __syncthreads();
    }
    if (tid == 0) {
        const float inv_n = 1.f / (float)(B_ * H_);
        float mean = rs[0] * inv_n;
        float var  = rq[0] * inv_n - mean * mean;
        float is   = rsqrtf(var + 1e-5f);
        float sc   = gamma[t] * is;
        g_scale[t] = sc;
        g_shift[t] = beta[t] - mean * sc;
    }
}

// ------------------------------------------------------------------
// Kernel 4: out[b,h] = mean_t elu(h[t,b,h]*scale[t] + shift[t])
// ------------------------------------------------------------------
__global__ void k_final(float* __restrict__ out)
{
    const int idx = blockIdx.x * 256 + threadIdx.x;   // b*512 + h
    float acc = 0.f;
    #pragma unroll 4
    for (int t = 0; t < T_; ++t) {
        float v = g_h[(size_t)t * (B_ * H_) + idx] * g_scale[t] + g_shift[t];
        acc += (v > 0.f) ? v : expm1f(v);
    }
    out[idx] = acc * (1.f / (float)T_);
}

// ------------------------------------------------------------------
extern "C" void kernel_launch(void* const* d_in, const int* in_sizes, int n_in,
                              void* d_out, int out_size)
{
    const float* x     = (const float*)d_in[0];
    const float* Wih   = (const float*)d_in[1];
    const float* Whh   = (const float*)d_in[2];
    const float* bih   = (const float*)d_in[3];
    const float* bhh   = (const float*)d_in[4];
    const float* gamma = (const float*)d_in[5];
    const float* beta  = (const float*)d_in[6];
    float* out = (float*)d_out;

    k_build_xg<<<(M_ * X_) / 256, 256>>>(x);
    k_gemm_pre<<<dim3(G_ / BN, M_ / BM), 256>>>(Wih, bih, bhh);
    for (int t = 0; t < T_; ++t)
        k_step<<<128, 256>>>(Whh, t);
    k_bnstats<<<T_, 256>>>(gamma, beta);
    k_final<<<(B_ * H_) / 256, 256>>>(out);
}

// round 6
// speedup vs baseline: 1.0023x; 1.0023x over previous
#include <cuda_runtime.h>
#include <math.h>

#define B_  64
#define T_  256
#define KX  5
#define X_  512
#define H_  512
#define G_  2048   // 4*H
#define F_  1024   // 2*X
#define M_  (B_*T_)

// ---- scratch (static device globals; no runtime allocation) ----
static __device__ float g_xg[(size_t)M_ * F_];          // 64 MB  (b*T+t, 1024)
static __device__ float g_pre[(size_t)T_ * B_ * G_];    // 128 MB (t, b, 2048)
static __device__ float g_h[(size_t)T_ * B_ * H_];      // 32 MB  (t, b, 512) == scan state + history
static __device__ float g_c[B_ * H_];                   // cell state, owner-indexed (race-free in place)
static __device__ float g_scale[T_];
static __device__ float g_shift[T_];

// ------------------------------------------------------------------
// Kernel 0: x_g_t = concat(x[:,:,0,:], mean(x[:,:,1:5,:], axis=2))
// ------------------------------------------------------------------
__global__ void k_build_xg(const float* __restrict__ x)
{
    int idx = blockIdx.x * blockDim.x + threadIdx.x;   // over M_*X_
    if (idx >= M_ * X_) return;
    int col = idx & (X_ - 1);
    int bt  = idx >> 9;                                // b*T + t
    const float* px = x + (size_t)bt * (KX * X_) + col;
    float s = px[0];
    float r = 0.25f * (px[X_] + px[2 * X_] + px[3 * X_] + px[4 * X_]);
    g_xg[(size_t)bt * F_ + col]       = s;
    g_xg[(size_t)bt * F_ + X_ + col]  = r;
}

// ------------------------------------------------------------------
// Kernel 1: pre[t][b][g] = sum_f xg[b*T+t][f] * W_ih[g][f] + (b_ih+b_hh)[g]
// Classic 128x128x8 fp32 SGEMM, 256 threads, 8x8 microtile (split 4+4).
// ------------------------------------------------------------------
#define BM 128
#define BN 128
#define BKK 8

__global__ __launch_bounds__(256, 2)
void k_gemm_pre(const float* __restrict__ Wih,
                const float* __restrict__ bih,
                const float* __restrict__ bhh)
{
    __shared__ float As[BKK][BM];
    __shared__ float Bs[BKK][BN];

    const int tid = threadIdx.x;
    const int m0 = blockIdx.y * BM;
    const int n0 = blockIdx.x * BN;

    // global->smem loaders: one float4 of A and B per thread per k-tile
    const int lr = tid >> 1;            // 0..127 : tile row
    const int lk = (tid & 1) << 2;      // 0 or 4 : k sub-offset

    // compute mapping: 16x16 thread grid, split microtile (4 + 4 at +64)
    const int tr = tid >> 4;            // 0..15
    const int tc = tid & 15;            // 0..15
    const int ra = tr << 2;
    const int cb = tc << 2;

    float acc[8][8];
    #pragma unroll
    for (int i = 0; i < 8; ++i)
        #pragma unroll
        for (int j = 0; j < 8; ++j) acc[i][j] = 0.f;

    const float* Aptr = &g_xg[(size_t)(m0 + lr) * F_ + lk];
    const float* Bptr = &Wih [(size_t)(n0 + lr) * F_ + lk];

    for (int k0 = 0; k0 < F_; k0 += BKK) {
        float4 av = *(const float4*)(Aptr + k0);
        float4 bv = *(const float4*)(Bptr + k0);
        As[lk + 0][lr] = av.x; As[lk + 1][lr] = av.y;
        As[lk + 2][lr] = av.z; As[lk + 3][lr] = av.w;
        Bs[lk + 0][lr] = bv.x; Bs[lk + 1][lr] = bv.y;
        Bs[lk + 2][lr] = bv.z; Bs[lk + 3][lr] = bv.w;
        __syncthreads();
        #pragma unroll
        for (int kk = 0; kk < BKK; ++kk) {
            float a[8], b[8];
            *(float4*)(a)     = *(const float4*)(&As[kk][ra]);
            *(float4*)(a + 4) = *(const float4*)(&As[kk][ra + 64]);
            *(float4*)(b)     = *(const float4*)(&Bs[kk][cb]);
            *(float4*)(b + 4) = *(const float4*)(&Bs[kk][cb + 64]);
            #pragma unroll
            for (int i = 0; i < 8; ++i)
                #pragma unroll
                for (int j = 0; j < 8; ++j)
                    acc[i][j] += a[i] * b[j];
        }
        __syncthreads();
    }

    // epilogue: add bias, permute (b*T+t, g) -> (t, b, g)
    float bias[8];
    #pragma unroll
    for (int j = 0; j < 8; ++j) {
        int col = n0 + cb + ((j < 4) ? j : 60 + j);
        bias[j] = bih[col] + bhh[col];
    }
    #pragma unroll
    for (int i = 0; i < 8; ++i) {
        int m = m0 + ra + ((i < 4) ? i : 60 + i);
        int t = m & (T_ - 1);
        int b = m >> 8;
        float* dst = &g_pre[((size_t)t * B_ + b) * G_ + n0];
        float4 v0 = make_float4(acc[i][0] + bias[0], acc[i][1] + bias[1],
                                acc[i][2] + bias[2], acc[i][3] + bias[3]);
        float4 v1 = make_float4(acc[i][4] + bias[4], acc[i][5] + bias[5],
                                acc[i][6] + bias[6], acc[i][7] + bias[7]);
        *(float4*)(dst + cb)      = v0;
        *(float4*)(dst + cb + 64) = v1;
    }
}

// ------------------------------------------------------------------
// Kernel 2: one LSTM time step. 128 CTAs x 256 threads.
// CTA owns j-range [j0, j0+4) across all 4 gates (16 W_hh rows in smem).
// Thread (b = tid&63, jj = tid>>6) computes all 4 gates for (b, j0+jj).
// t=0: skips recurrent GEMM and cell read => no state init kernels needed.
// ------------------------------------------------------------------
#define SBK 32

__global__ __launch_bounds__(256)
void k_step(const float* __restrict__ Whh, int t)
{
    __shared__ float Ws[16][H_];          // 32 KB : 16 W_hh rows (gate*4+jj)
    __shared__ float Hs[64][SBK + 4];     // 9.2 KB: h chunk, padded (4b+k banks)

    const int tid = threadIdx.x;
    const int j0 = blockIdx.x << 2;
    const int b  = tid & 63;
    const int jj = tid >> 6;
    const int j  = j0 + jj;

    float acc0 = 0.f, acc1 = 0.f, acc2 = 0.f, acc3 = 0.f;

    if (t > 0) {
        // load 16 rows of W_hh: row_local rl = gate*4 + jjl -> global row gate*512 + j0 + jjl
        for (int i = tid; i < 16 * (H_ / 4); i += 256) {
            int rl = i >> 7;                  // 128 float4 per row
            int k4 = (i & 127) << 2;
            int grow = (rl >> 2) * H_ + j0 + (rl & 3);
            *(float4*)&Ws[rl][k4] = *(const float4*)&Whh[(size_t)grow * H_ + k4];
        }

        const float* hprev = &g_h[(size_t)(t - 1) * (B_ * H_)];
        for (int kc = 0; kc < H_; kc += SBK) {
            __syncthreads();
            // load 64 x 32 h chunk (coalesced float4 over k)
            for (int i = tid; i < 512; i += 256) {
                int bb = i >> 3;
                int k4 = (i & 7) << 2;
                *(float4*)&Hs[bb][k4] = *(const float4*)&hprev[(size_t)bb * H_ + kc + k4];
            }
            __syncthreads();
            #pragma unroll
            for (int k = 0; k < SBK; k += 4) {
                float4 a  = *(const float4*)&Hs[b][k];
                float4 w0 = *(const float4*)&Ws[jj     ][kc + k];
                float4 w1 = *(const float4*)&Ws[jj + 4 ][kc + k];
                float4 w2 = *(const float4*)&Ws[jj + 8 ][kc + k];
                float4 w3 = *(const float4*)&Ws[jj + 12][kc + k];
                acc0 += a.x * w0.x; acc0 += a.y * w0.y; acc0 += a.z * w0.z; acc0 += a.w * w0.w;
                acc1 += a.x * w1.x; acc1 += a.y * w1.y; acc1 += a.z * w1.z; acc1 += a.w * w1.w;
                acc2 += a.x * w2.x; acc2 += a.y * w2.y; acc2 += a.z * w2.z; acc2 += a.w * w2.w;
                acc3 += a.x * w3.x; acc3 += a.y * w3.y; acc3 += a.z * w3.z; acc3 += a.w * w3.w;
            }
        }
    }

    const float* prow = &g_pre[((size_t)t * B_ + b) * G_];
    float zi = acc0 + prow[j];
    float zf = acc1 + prow[j + 512];
    float zg = acc2 + prow[j + 1024];
    float zo = acc3 + prow[j + 1536];

    float ig = 1.f / (1.f + expf(-zi));
    float fg = 1.f / (1.f + expf(-zf));
    float gg = tanhf(zg);
    float og = 1.f / (1.f + expf(-zo));

    const int cidx = b * H_ + j;
    float cprev = (t > 0) ? g_c[cidx] : 0.f;
    float c = fg * cprev + ig * gg;
    g_c[cidx] = c;
    g_h[(size_t)t * (B_ * H_) + cidx] = og * tanhf(c);
}

// ------------------------------------------------------------------
// Kernel 3: per-t batchnorm stats over (B,H) -> scale/shift
// ------------------------------------------------------------------
__global__ void k_bnstats(const float* __restrict__ gamma,
                          const float* __restrict__ beta)
{
    const int t   = blockIdx.x;
    const int tid = threadIdx.x;
    const float* p = &g_h[(size_t)t * (B_ * H_)];
    float s = 0.f, s2 = 0.f;
    for (int i = tid; i < B_ * H_; i += 256) {
        float v = p[i];
        s += v; s2 += v * v;
    }
    __shared__ float rs[256], rq[256];
    rs[tid] = s; rq[tid] = s2;
    __syncthreads();
    for (int off = 128; off > 0; off >>= 1) {
        if (tid < off) { rs[tid] += rs[tid + off]; rq[tid] += rq[tid + off]; }
        __syncthreads();
    }
    if (tid == 0) {
        const float inv_n = 1.f / (float)(B_ * H_);
        float mean = rs[0] * inv_n;
        float var  = rq[0] * inv_n - mean * mean;
        float is   = rsqrtf(var + 1e-5f);
        float sc   = gamma[t] * is;
        g_scale[t] = sc;
        g_shift[t] = beta[t] - mean * sc;
    }
}

// ------------------------------------------------------------------
// Kernel 4: out[b,h] = mean_t elu(h[t,b,h]*scale[t] + shift[t])
// ------------------------------------------------------------------
__global__ void k_final(float* __restrict__ out)
{
    const int idx = blockIdx.x * 256 + threadIdx.x;   // b*512 + h
    float acc = 0.f;
    #pragma unroll 4
    for (int t = 0; t < T_; ++t) {
        float v = g_h[(size_t)t * (B_ * H_) + idx] * g_scale[t] + g_shift[t];
        acc += (v > 0.f) ? v : expm1f(v);
    }
    out[idx] = acc * (1.f / (float)T_);
}

// ------------------------------------------------------------------
extern "C" void kernel_launch(void* const* d_in, const int* in_sizes, int n_in,
                              void* d_out, int out_size)
{
    const float* x     = (const float*)d_in[0];
    const float* Wih   = (const float*)d_in[1];
    const float* Whh   = (const float*)d_in[2];
    const float* bih   = (const float*)d_in[3];
    const float* bhh   = (const float*)d_in[4];
    const float* gamma = (const float*)d_in[5];
    const float* beta  = (const float*)d_in[6];
    float* out = (float*)d_out;

    k_build_xg<<<(M_ * X_) / 256, 256>>>(x);
    k_gemm_pre<<<dim3(G_ / BN, M_ / BM), 256>>>(Wih, bih, bhh);
    for (int t = 0; t < T_; ++t)
        k_step<<<128, 256>>>(Whh, t);
    k_bnstats<<<T_, 256>>>(gamma, beta);
    k_final<<<(B_ * H_) / 256, 256>>>(out);
}